// round 2
// baseline (speedup 1.0000x reference)
#include <cuda_runtime.h>
#include <math.h>

// ---------------------------------------------------------------------------
// DscaGRUCell — fp32 SIMT, corrected (r * h_prev) @ rk_h precedence
// B=4096, D1=D2=2000, E1=E2=256, U=512, M=512
// ---------------------------------------------------------------------------

namespace {
constexpr int BROWS   = 4096;
constexpr int EDIM    = 256;
constexpr int UDIM    = 512;
constexpr int DDIM    = 2000;
constexpr int THREEU  = 1536;
}

// ------------------------------ scratch (device globals; no allocs) --------
__device__ float g_Wpack[2 * DDIM * EDIM];        // [W1 ; W2]
__device__ float g_P[2 * 2 * EDIM * EDIM];        // [P12(512x256) ; P21(512x256)]
__device__ float g_Pv[2 * EDIM * EDIM];           // [v12 ; v21]
__device__ float g_Kpack[2 * UDIM * THREEU];      // [kernel ; recurrent_kernel]
__device__ float g_biaspack[2 * THREEU];          // [bias ; zeros]
__device__ float g_emb[BROWS * 2 * EDIM];         // [emb1 | emb2], ld=512
__device__ float g_S[2 * BROWS * EDIM];           // S12, S21
__device__ float g_V[2 * BROWS * EDIM];           // V12, V21
__device__ float g_xh[2 * BROWS * UDIM];          // [x ; h_prev]
__device__ float g_cro[BROWS * UDIM];
__device__ float g_mxi[2 * BROWS * THREEU];       // [mx ; mi]
__device__ float g_rh[BROWS * UDIM];              // r * h_prev
__device__ float g_mh[BROWS * UDIM];              // (r*h_prev) @ rk[:,2U:]

// ------------------------------ pack: pure concatenations ------------------
__global__ void pack_kernel(
    const float* __restrict__ W1, const float* __restrict__ W2,
    const float* __restrict__ w12, const float* __restrict__ u12, const float* __restrict__ v12,
    const float* __restrict__ w21, const float* __restrict__ u21, const float* __restrict__ v21,
    const float* __restrict__ kern, const float* __restrict__ rkern,
    const float* __restrict__ bias)
{
    int idx = blockIdx.x * blockDim.x + threadIdx.x;
    const int nW = DDIM * EDIM;      // 512000
    const int nE = EDIM * EDIM;      // 65536
    const int nK = UDIM * THREEU;    // 786432
    if (idx < nW)        { g_Wpack[idx] = W1[idx]; return; }           idx -= nW;
    if (idx < nW)        { g_Wpack[nW + idx] = W2[idx]; return; }      idx -= nW;
    if (idx < nE)        { g_P[idx]          = w12[idx]; return; }     idx -= nE;
    if (idx < nE)        { g_P[nE + idx]     = u12[idx]; return; }     idx -= nE;
    if (idx < nE)        { g_P[2*nE + idx]   = u21[idx]; return; }     idx -= nE;
    if (idx < nE)        { g_P[3*nE + idx]   = w21[idx]; return; }     idx -= nE;
    if (idx < nE)        { g_Pv[idx]         = v12[idx]; return; }     idx -= nE;
    if (idx < nE)        { g_Pv[nE + idx]    = v21[idx]; return; }     idx -= nE;
    if (idx < nK)        { g_Kpack[idx]      = kern[idx]; return; }    idx -= nK;
    if (idx < nK)        { g_Kpack[nK + idx] = rkern[idx]; return; }   idx -= nK;
    if (idx < THREEU)    { g_biaspack[idx] = bias[idx]; return; }      idx -= THREEU;
    if (idx < THREEU)    { g_biaspack[THREEU + idx] = 0.0f; return; }
}

// ------------------------------ GEMM: 128x128x8, 256 thr, 8x8/thread -------
// EPI: 0 = store, 1 = +bias, 2 = tanh(acc+bias), 3 = add + tanh(acc+bias)
template <int EPI>
__global__ void __launch_bounds__(256)
gemm_kernel(const float* __restrict__ A, int lda, long long aZ,
            const float* __restrict__ Bm, int ldb, long long bZ,
            float* __restrict__ C, int ldc, long long cZ,
            int K,
            const float* __restrict__ bias, int biasZ,
            const float* __restrict__ add, int ldadd)
{
    A  += (long long)blockIdx.z * aZ;
    Bm += (long long)blockIdx.z * bZ;
    C  += (long long)blockIdx.z * cZ;
    if (EPI == 1 || EPI == 2 || EPI == 3) bias += (long long)blockIdx.z * biasZ;

    __shared__ float As[8][128];
    __shared__ float Bs[8][128];
    const int tid  = threadIdx.x;
    const int bm   = blockIdx.y * 128;
    const int bn   = blockIdx.x * 128;
    const int arow = tid >> 1;
    const int acol = (tid & 1) << 2;
    const int brow = tid >> 5;
    const int bcol = (tid & 31) << 2;
    const int tx   = tid & 15;
    const int ty   = tid >> 4;

    const float* Ap = A  + (long long)(bm + arow) * lda + acol;
    const float* Bp = Bm + (long long)brow * ldb + bn + bcol;

    float acc[8][8];
    #pragma unroll
    for (int i = 0; i < 8; i++)
        #pragma unroll
        for (int j = 0; j < 8; j++) acc[i][j] = 0.0f;

    for (int k0 = 0; k0 < K; k0 += 8) {
        float4 av = *(const float4*)Ap;
        float4 bv = *(const float4*)Bp;
        As[acol + 0][arow] = av.x;
        As[acol + 1][arow] = av.y;
        As[acol + 2][arow] = av.z;
        As[acol + 3][arow] = av.w;
        *(float4*)&Bs[brow][bcol] = bv;
        __syncthreads();
        #pragma unroll
        for (int kk = 0; kk < 8; kk++) {
            float a[8], b[8];
            *(float4*)&a[0] = *(const float4*)&As[kk][ty * 8];
            *(float4*)&a[4] = *(const float4*)&As[kk][ty * 8 + 4];
            *(float4*)&b[0] = *(const float4*)&Bs[kk][tx * 8];
            *(float4*)&b[4] = *(const float4*)&Bs[kk][tx * 8 + 4];
            #pragma unroll
            for (int i = 0; i < 8; i++)
                #pragma unroll
                for (int j = 0; j < 8; j++)
                    acc[i][j] = fmaf(a[i], b[j], acc[i][j]);
        }
        __syncthreads();
        Ap += 8;
        Bp += (long long)8 * ldb;
    }

    #pragma unroll
    for (int i = 0; i < 8; i++) {
        const int row = bm + ty * 8 + i;
        #pragma unroll
        for (int j = 0; j < 8; j++) {
            const int col = bn + tx * 8 + j;
            float v = acc[i][j];
            if (EPI == 1)      v += bias[col];
            else if (EPI == 2) v = tanhf(v + bias[col]);
            else if (EPI == 3) v = add[(long long)row * ldadd + col] + tanhf(v + bias[col]);
            C[(long long)row * ldc + col] = v;
        }
    }
}

// ------------------------------ attention + crohis_new ---------------------
// one block per row; 256 threads; handles both attention sides sequentially
__global__ void __launch_bounds__(256)
attn_kernel(const float* __restrict__ crohis_tm, float* __restrict__ out_crohis)
{
    __shared__ float red[256];
    const int row = blockIdx.x;
    const int c   = threadIdx.x;
    const float* emb = g_emb + (long long)row * 512;

    #pragma unroll
    for (int side = 0; side < 2; side++) {
        const float* S = g_S + (long long)side * (BROWS * EDIM) + (long long)row * 256;
        const float* V = g_V + (long long)side * (BROWS * EDIM) + (long long)row * 256;
        float l = tanhf(S[c]) * V[c];
        red[c] = l; __syncthreads();
        #pragma unroll
        for (int s = 128; s > 0; s >>= 1) {
            if (c < s) red[c] = fmaxf(red[c], red[c + s]);
            __syncthreads();
        }
        float m = red[0]; __syncthreads();
        float e = __expf(l - m);
        red[c] = e; __syncthreads();
        #pragma unroll
        for (int s = 128; s > 0; s >>= 1) {
            if (c < s) red[c] += red[c + s];
            __syncthreads();
        }
        float ssum = red[0]; __syncthreads();
        float att = e / ssum;
        int col = side * 256 + c;
        float xv = emb[col] * att;
        long long gidx = (long long)row * 512 + col;
        g_xh[gidx] = xv;
        out_crohis[gidx] = 0.5f * crohis_tm[gidx] + 0.5f * xv;
    }
}

// ------------------------------ r gate + r*h_prev ---------------------------
__global__ void rgate_kernel()
{
    int idx = blockIdx.x * blockDim.x + threadIdx.x;
    if (idx >= BROWS * UDIM) return;
    int row = idx >> 9;
    int col = idx & 511;
    const float* mx = g_mxi + (long long)row * THREEU;
    const float* mi = g_mxi + (long long)BROWS * THREEU + (long long)row * THREEU;
    float r  = 1.0f / (1.0f + __expf(-(mx[col + 512] + mi[col + 512])));
    float hp = g_xh[(long long)(BROWS * UDIM) + idx];
    g_rh[idx] = r * hp;
}

// ------------------------------ GRU combine --------------------------------
__global__ void gru_kernel(float* __restrict__ h_out)
{
    int idx = blockIdx.x * blockDim.x + threadIdx.x;
    if (idx >= BROWS * UDIM) return;
    int row = idx >> 9;          // /512
    int col = idx & 511;
    const float* mx = g_mxi + (long long)row * THREEU;
    const float* mi = g_mxi + (long long)BROWS * THREEU + (long long)row * THREEU;
    float z  = 1.0f / (1.0f + __expf(-(mx[col] + mi[col])));
    float hp = g_xh[(long long)(BROWS * UDIM) + idx];
    float hh = tanhf(mx[col + 1024] + g_mh[idx]);
    h_out[idx] = z * hp + (1.0f - z) * hh;
}

// ------------------------------ launch ------------------------------------
extern "C" void kernel_launch(void* const* d_in, const int* in_sizes, int n_in,
                              void* d_out, int out_size)
{
    const float* inputs    = (const float*)d_in[0];
    const float* h_tm1     = (const float*)d_in[1];
    const float* crohis_tm = (const float*)d_in[2];
    const float* W1        = (const float*)d_in[3];
    const float* W2        = (const float*)d_in[4];
    const float* w12       = (const float*)d_in[5];
    const float* u12       = (const float*)d_in[6];
    const float* v12       = (const float*)d_in[7];
    const float* w21       = (const float*)d_in[8];
    const float* u21       = (const float*)d_in[9];
    const float* v21       = (const float*)d_in[10];
    const float* croW      = (const float*)d_in[11];
    const float* croB      = (const float*)d_in[12];
    const float* decompW   = (const float*)d_in[13];
    const float* decompB   = (const float*)d_in[14];
    const float* kern      = (const float*)d_in[15];
    const float* rkern     = (const float*)d_in[16];
    const float* bias      = (const float*)d_in[17];
    float* out = (float*)d_out;

    float *pW, *pP, *pPv, *pK, *pB, *pEmb, *pS, *pV, *pXH, *pCro, *pMXI, *pRH, *pMH;
    cudaGetSymbolAddress((void**)&pW,   g_Wpack);
    cudaGetSymbolAddress((void**)&pP,   g_P);
    cudaGetSymbolAddress((void**)&pPv,  g_Pv);
    cudaGetSymbolAddress((void**)&pK,   g_Kpack);
    cudaGetSymbolAddress((void**)&pB,   g_biaspack);
    cudaGetSymbolAddress((void**)&pEmb, g_emb);
    cudaGetSymbolAddress((void**)&pS,   g_S);
    cudaGetSymbolAddress((void**)&pV,   g_V);
    cudaGetSymbolAddress((void**)&pXH,  g_xh);
    cudaGetSymbolAddress((void**)&pCro, g_cro);
    cudaGetSymbolAddress((void**)&pMXI, g_mxi);
    cudaGetSymbolAddress((void**)&pRH,  g_rh);
    cudaGetSymbolAddress((void**)&pMH,  g_mh);

    const long long BU = (long long)BROWS * UDIM;       // 2097152
    const int packTotal = 2*DDIM*EDIM + 4*EDIM*EDIM + 2*EDIM*EDIM
                        + 2*UDIM*THREEU + 2*THREEU;     // 2,993,152

    // 1. pack weights
    pack_kernel<<<(packTotal + 255) / 256, 256>>>(W1, W2, w12, u12, v12,
                                                  w21, u21, v21, kern, rkern, bias);

    // 2. emb{1,2} = inputs[:, z*2000 : ] @ W{z}   (z-batched, K=2000)
    gemm_kernel<0><<<dim3(2, 32, 2), 256>>>(inputs, 4000, 2000,
                                            pW, 256, (long long)DDIM*EDIM,
                                            pEmb, 512, 256,
                                            2000, nullptr, 0, nullptr, 0);

    // 3. S{12,21} = emb @ P{12,21}   (z-batched, K=512)
    gemm_kernel<0><<<dim3(2, 32, 2), 256>>>(pEmb, 512, 0,
                                            pP, 256, (long long)2*EDIM*EDIM,
                                            pS, 256, (long long)BROWS*EDIM,
                                            512, nullptr, 0, nullptr, 0);

    // 4. V12 = emb2 @ v12, V21 = emb1 @ v21   (z-batched via aZ=-256, K=256)
    gemm_kernel<0><<<dim3(2, 32, 2), 256>>>(pEmb + 256, 512, -256,
                                            pPv, 256, (long long)EDIM*EDIM,
                                            pV, 256, (long long)BROWS*EDIM,
                                            256, nullptr, 0, nullptr, 0);

    // 5. attention softmax + gating + crohis_new (second half of d_out)
    attn_kernel<<<BROWS, 256>>>(crohis_tm, out + BU);

    // 6. cro = tanh(crohis_tm @ decompW + decompB)
    gemm_kernel<2><<<dim3(4, 32, 1), 256>>>(crohis_tm, 512, 0,
                                            decompW, 512, 0,
                                            pCro, 512, 0,
                                            512, decompB, 0, nullptr, 0);

    // 7. h_prev = h_tm1 + tanh(cro @ croW + croB)  -> g_xh second half
    gemm_kernel<3><<<dim3(4, 32, 1), 256>>>(pCro, 512, 0,
                                            croW, 512, 0,
                                            pXH + BU, 512, 0,
                                            512, croB, 0, h_tm1, 512);

    // 8. mx = x @ kernel + bias ; mi = h_prev @ rkern  (z-batched, K=512)
    //    (mi's last-512 columns are computed but unused — hh uses (r*h_prev)@rk_h)
    gemm_kernel<1><<<dim3(12, 32, 2), 256>>>(pXH, 512, BU,
                                             pK, 1536, (long long)UDIM*THREEU,
                                             pMXI, 1536, (long long)BROWS*THREEU,
                                             512, pB, THREEU, nullptr, 0);

    // 9. r = sigmoid(mx_r + mi_r); rh = r * h_prev
    rgate_kernel<<<(BROWS * UDIM + 255) / 256, 256>>>();

    // 10. mh = (r*h_prev) @ recurrent_kernel[:, 2U:]   (K=512, N=512)
    gemm_kernel<0><<<dim3(4, 32, 1), 256>>>(pRH, 512, 0,
                                            rkern + 1024, 1536, 0,
                                            pMH, 512, 0,
                                            512, nullptr, 0, nullptr, 0);

    // 11. GRU combine -> h (first half of d_out)
    gru_kernel<<<(BROWS * UDIM + 255) / 256, 256>>>(out);
}

// round 3
// speedup vs baseline: 1.0002x; 1.0002x over previous
#include <cuda_runtime.h>
#include <math.h>

// ---------------------------------------------------------------------------
// DscaGRUCell — fp32 SIMT, corrected (r * h_prev) @ rk_h precedence
// B=4096, D1=D2=2000, E1=E2=256, U=512, M=512
// ---------------------------------------------------------------------------

namespace {
constexpr int BROWS   = 4096;
constexpr int EDIM    = 256;
constexpr int UDIM    = 512;
constexpr int DDIM    = 2000;
constexpr int THREEU  = 1536;
}

// ------------------------------ scratch (device globals; no allocs) --------
__device__ float g_Wpack[2 * DDIM * EDIM];        // [W1 ; W2]
__device__ float g_P[2 * 2 * EDIM * EDIM];        // [P12(512x256) ; P21(512x256)]
__device__ float g_Pv[2 * EDIM * EDIM];           // [v12 ; v21]
__device__ float g_Kpack[2 * UDIM * THREEU];      // [kernel ; recurrent_kernel]
__device__ float g_biaspack[2 * THREEU];          // [bias ; zeros]
__device__ float g_emb[BROWS * 2 * EDIM];         // [emb1 | emb2], ld=512
__device__ float g_S[2 * BROWS * EDIM];           // S12, S21
__device__ float g_V[2 * BROWS * EDIM];           // V12, V21
__device__ float g_xh[2 * BROWS * UDIM];          // [x ; h_prev]
__device__ float g_cro[BROWS * UDIM];
__device__ float g_mxi[2 * BROWS * THREEU];       // [mx ; mi]
__device__ float g_rh[BROWS * UDIM];              // r * h_prev
__device__ float g_mh[BROWS * UDIM];              // (r*h_prev) @ rk[:,2U:]

// ------------------------------ pack: pure concatenations ------------------
__global__ void pack_kernel(
    const float* __restrict__ W1, const float* __restrict__ W2,
    const float* __restrict__ w12, const float* __restrict__ u12, const float* __restrict__ v12,
    const float* __restrict__ w21, const float* __restrict__ u21, const float* __restrict__ v21,
    const float* __restrict__ kern, const float* __restrict__ rkern,
    const float* __restrict__ bias)
{
    int idx = blockIdx.x * blockDim.x + threadIdx.x;
    const int nW = DDIM * EDIM;      // 512000
    const int nE = EDIM * EDIM;      // 65536
    const int nK = UDIM * THREEU;    // 786432
    if (idx < nW)        { g_Wpack[idx] = W1[idx]; return; }           idx -= nW;
    if (idx < nW)        { g_Wpack[nW + idx] = W2[idx]; return; }      idx -= nW;
    if (idx < nE)        { g_P[idx]          = w12[idx]; return; }     idx -= nE;
    if (idx < nE)        { g_P[nE + idx]     = u12[idx]; return; }     idx -= nE;
    if (idx < nE)        { g_P[2*nE + idx]   = u21[idx]; return; }     idx -= nE;
    if (idx < nE)        { g_P[3*nE + idx]   = w21[idx]; return; }     idx -= nE;
    if (idx < nE)        { g_Pv[idx]         = v12[idx]; return; }     idx -= nE;
    if (idx < nE)        { g_Pv[nE + idx]    = v21[idx]; return; }     idx -= nE;
    if (idx < nK)        { g_Kpack[idx]      = kern[idx]; return; }    idx -= nK;
    if (idx < nK)        { g_Kpack[nK + idx] = rkern[idx]; return; }   idx -= nK;
    if (idx < THREEU)    { g_biaspack[idx] = bias[idx]; return; }      idx -= THREEU;
    if (idx < THREEU)    { g_biaspack[THREEU + idx] = 0.0f; return; }
}

// ------------------------------ GEMM: 128x128x8, 256 thr, 8x8/thread -------
// EPI: 0 = store, 1 = +bias, 2 = tanh(acc+bias), 3 = add + tanh(acc+bias)
template <int EPI>
__global__ void __launch_bounds__(256)
gemm_kernel(const float* __restrict__ A, int lda, long long aZ,
            const float* __restrict__ Bm, int ldb, long long bZ,
            float* __restrict__ C, int ldc, long long cZ,
            int K,
            const float* __restrict__ bias, int biasZ,
            const float* __restrict__ add, int ldadd)
{
    A  += (long long)blockIdx.z * aZ;
    Bm += (long long)blockIdx.z * bZ;
    C  += (long long)blockIdx.z * cZ;
    if (EPI == 1 || EPI == 2 || EPI == 3) bias += (long long)blockIdx.z * biasZ;

    __shared__ float As[8][128];
    __shared__ float Bs[8][128];
    const int tid  = threadIdx.x;
    const int bm   = blockIdx.y * 128;
    const int bn   = blockIdx.x * 128;
    const int arow = tid >> 1;
    const int acol = (tid & 1) << 2;
    const int brow = tid >> 5;
    const int bcol = (tid & 31) << 2;
    const int tx   = tid & 15;
    const int ty   = tid >> 4;

    const float* Ap = A  + (long long)(bm + arow) * lda + acol;
    const float* Bp = Bm + (long long)brow * ldb + bn + bcol;

    float acc[8][8];
    #pragma unroll
    for (int i = 0; i < 8; i++)
        #pragma unroll
        for (int j = 0; j < 8; j++) acc[i][j] = 0.0f;

    for (int k0 = 0; k0 < K; k0 += 8) {
        float4 av = *(const float4*)Ap;
        float4 bv = *(const float4*)Bp;
        As[acol + 0][arow] = av.x;
        As[acol + 1][arow] = av.y;
        As[acol + 2][arow] = av.z;
        As[acol + 3][arow] = av.w;
        *(float4*)&Bs[brow][bcol] = bv;
        __syncthreads();
        #pragma unroll
        for (int kk = 0; kk < 8; kk++) {
            float a[8], b[8];
            *(float4*)&a[0] = *(const float4*)&As[kk][ty * 8];
            *(float4*)&a[4] = *(const float4*)&As[kk][ty * 8 + 4];
            *(float4*)&b[0] = *(const float4*)&Bs[kk][tx * 8];
            *(float4*)&b[4] = *(const float4*)&Bs[kk][tx * 8 + 4];
            #pragma unroll
            for (int i = 0; i < 8; i++)
                #pragma unroll
                for (int j = 0; j < 8; j++)
                    acc[i][j] = fmaf(a[i], b[j], acc[i][j]);
        }
        __syncthreads();
        Ap += 8;
        Bp += (long long)8 * ldb;
    }

    #pragma unroll
    for (int i = 0; i < 8; i++) {
        const int row = bm + ty * 8 + i;
        #pragma unroll
        for (int j = 0; j < 8; j++) {
            const int col = bn + tx * 8 + j;
            float v = acc[i][j];
            if (EPI == 1)      v += bias[col];
            else if (EPI == 2) v = tanhf(v + bias[col]);
            else if (EPI == 3) v = add[(long long)row * ldadd + col] + tanhf(v + bias[col]);
            C[(long long)row * ldc + col] = v;
        }
    }
}

// ------------------------------ attention + crohis_new ---------------------
// one block per row; 256 threads; handles both attention sides sequentially
__global__ void __launch_bounds__(256)
attn_kernel(const float* __restrict__ crohis_tm, float* __restrict__ out_crohis)
{
    __shared__ float red[256];
    const int row = blockIdx.x;
    const int c   = threadIdx.x;
    const float* emb = g_emb + (long long)row * 512;

    #pragma unroll
    for (int side = 0; side < 2; side++) {
        const float* S = g_S + (long long)side * (BROWS * EDIM) + (long long)row * 256;
        const float* V = g_V + (long long)side * (BROWS * EDIM) + (long long)row * 256;
        float l = tanhf(S[c]) * V[c];
        red[c] = l; __syncthreads();
        #pragma unroll
        for (int s = 128; s > 0; s >>= 1) {
            if (c < s) red[c] = fmaxf(red[c], red[c + s]);
            __syncthreads();
        }
        float m = red[0]; __syncthreads();
        float e = __expf(l - m);
        red[c] = e; __syncthreads();
        #pragma unroll
        for (int s = 128; s > 0; s >>= 1) {
            if (c < s) red[c] += red[c + s];
            __syncthreads();
        }
        float ssum = red[0]; __syncthreads();
        float att = e / ssum;
        int col = side * 256 + c;
        float xv = emb[col] * att;
        long long gidx = (long long)row * 512 + col;
        g_xh[gidx] = xv;
        out_crohis[gidx] = 0.5f * crohis_tm[gidx] + 0.5f * xv;
    }
}

// ------------------------------ r gate + r*h_prev ---------------------------
__global__ void rgate_kernel()
{
    int idx = blockIdx.x * blockDim.x + threadIdx.x;
    if (idx >= BROWS * UDIM) return;
    int row = idx >> 9;
    int col = idx & 511;
    const float* mx = g_mxi + (long long)row * THREEU;
    const float* mi = g_mxi + (long long)BROWS * THREEU + (long long)row * THREEU;
    float r  = 1.0f / (1.0f + __expf(-(mx[col + 512] + mi[col + 512])));
    float hp = g_xh[(long long)(BROWS * UDIM) + idx];
    g_rh[idx] = r * hp;
}

// ------------------------------ GRU combine --------------------------------
__global__ void gru_kernel(float* __restrict__ h_out)
{
    int idx = blockIdx.x * blockDim.x + threadIdx.x;
    if (idx >= BROWS * UDIM) return;
    int row = idx >> 9;          // /512
    int col = idx & 511;
    const float* mx = g_mxi + (long long)row * THREEU;
    const float* mi = g_mxi + (long long)BROWS * THREEU + (long long)row * THREEU;
    float z  = 1.0f / (1.0f + __expf(-(mx[col] + mi[col])));
    float hp = g_xh[(long long)(BROWS * UDIM) + idx];
    float hh = tanhf(mx[col + 1024] + g_mh[idx]);
    h_out[idx] = z * hp + (1.0f - z) * hh;
}

// ------------------------------ launch ------------------------------------
extern "C" void kernel_launch(void* const* d_in, const int* in_sizes, int n_in,
                              void* d_out, int out_size)
{
    const float* inputs    = (const float*)d_in[0];
    const float* h_tm1     = (const float*)d_in[1];
    const float* crohis_tm = (const float*)d_in[2];
    const float* W1        = (const float*)d_in[3];
    const float* W2        = (const float*)d_in[4];
    const float* w12       = (const float*)d_in[5];
    const float* u12       = (const float*)d_in[6];
    const float* v12       = (const float*)d_in[7];
    const float* w21       = (const float*)d_in[8];
    const float* u21       = (const float*)d_in[9];
    const float* v21       = (const float*)d_in[10];
    const float* croW      = (const float*)d_in[11];
    const float* croB      = (const float*)d_in[12];
    const float* decompW   = (const float*)d_in[13];
    const float* decompB   = (const float*)d_in[14];
    const float* kern      = (const float*)d_in[15];
    const float* rkern     = (const float*)d_in[16];
    const float* bias      = (const float*)d_in[17];
    float* out = (float*)d_out;

    float *pW, *pP, *pPv, *pK, *pB, *pEmb, *pS, *pV, *pXH, *pCro, *pMXI, *pRH, *pMH;
    cudaGetSymbolAddress((void**)&pW,   g_Wpack);
    cudaGetSymbolAddress((void**)&pP,   g_P);
    cudaGetSymbolAddress((void**)&pPv,  g_Pv);
    cudaGetSymbolAddress((void**)&pK,   g_Kpack);
    cudaGetSymbolAddress((void**)&pB,   g_biaspack);
    cudaGetSymbolAddress((void**)&pEmb, g_emb);
    cudaGetSymbolAddress((void**)&pS,   g_S);
    cudaGetSymbolAddress((void**)&pV,   g_V);
    cudaGetSymbolAddress((void**)&pXH,  g_xh);
    cudaGetSymbolAddress((void**)&pCro, g_cro);
    cudaGetSymbolAddress((void**)&pMXI, g_mxi);
    cudaGetSymbolAddress((void**)&pRH,  g_rh);
    cudaGetSymbolAddress((void**)&pMH,  g_mh);

    const long long BU = (long long)BROWS * UDIM;       // 2097152
    const int packTotal = 2*DDIM*EDIM + 4*EDIM*EDIM + 2*EDIM*EDIM
                        + 2*UDIM*THREEU + 2*THREEU;     // 2,993,152

    // 1. pack weights
    pack_kernel<<<(packTotal + 255) / 256, 256>>>(W1, W2, w12, u12, v12,
                                                  w21, u21, v21, kern, rkern, bias);

    // 2. emb{1,2} = inputs[:, z*2000 : ] @ W{z}   (z-batched, K=2000)
    gemm_kernel<0><<<dim3(2, 32, 2), 256>>>(inputs, 4000, 2000,
                                            pW, 256, (long long)DDIM*EDIM,
                                            pEmb, 512, 256,
                                            2000, nullptr, 0, nullptr, 0);

    // 3. S{12,21} = emb @ P{12,21}   (z-batched, K=512)
    gemm_kernel<0><<<dim3(2, 32, 2), 256>>>(pEmb, 512, 0,
                                            pP, 256, (long long)2*EDIM*EDIM,
                                            pS, 256, (long long)BROWS*EDIM,
                                            512, nullptr, 0, nullptr, 0);

    // 4. V12 = emb2 @ v12, V21 = emb1 @ v21   (z-batched via aZ=-256, K=256)
    gemm_kernel<0><<<dim3(2, 32, 2), 256>>>(pEmb + 256, 512, -256,
                                            pPv, 256, (long long)EDIM*EDIM,
                                            pV, 256, (long long)BROWS*EDIM,
                                            256, nullptr, 0, nullptr, 0);

    // 5. attention softmax + gating + crohis_new (second half of d_out)
    attn_kernel<<<BROWS, 256>>>(crohis_tm, out + BU);

    // 6. cro = tanh(crohis_tm @ decompW + decompB)
    gemm_kernel<2><<<dim3(4, 32, 1), 256>>>(crohis_tm, 512, 0,
                                            decompW, 512, 0,
                                            pCro, 512, 0,
                                            512, decompB, 0, nullptr, 0);

    // 7. h_prev = h_tm1 + tanh(cro @ croW + croB)  -> g_xh second half
    gemm_kernel<3><<<dim3(4, 32, 1), 256>>>(pCro, 512, 0,
                                            croW, 512, 0,
                                            pXH + BU, 512, 0,
                                            512, croB, 0, h_tm1, 512);

    // 8. mx = x @ kernel + bias ; mi = h_prev @ rkern  (z-batched, K=512)
    //    (mi's last-512 columns are computed but unused — hh uses (r*h_prev)@rk_h)
    gemm_kernel<1><<<dim3(12, 32, 2), 256>>>(pXH, 512, BU,
                                             pK, 1536, (long long)UDIM*THREEU,
                                             pMXI, 1536, (long long)BROWS*THREEU,
                                             512, pB, THREEU, nullptr, 0);

    // 9. r = sigmoid(mx_r + mi_r); rh = r * h_prev
    rgate_kernel<<<(BROWS * UDIM + 255) / 256, 256>>>();

    // 10. mh = (r*h_prev) @ recurrent_kernel[:, 2U:]   (K=512, N=512)
    gemm_kernel<0><<<dim3(4, 32, 1), 256>>>(pRH, 512, 0,
                                            rkern + 1024, 1536, 0,
                                            pMH, 512, 0,
                                            512, nullptr, 0, nullptr, 0);

    // 11. GRU combine -> h (first half of d_out)
    gru_kernel<<<(BROWS * UDIM + 255) / 256, 256>>>(out);
}

// round 5
// speedup vs baseline: 1.8855x; 1.8851x over previous
#include <cuda_runtime.h>
#include <cuda_bf16.h>
#include <math.h>
#include <stdint.h>

namespace {
constexpr int BROWS  = 4096;
constexpr int UDIM   = 512;
constexpr int THREEU = 1536;
constexpr long long BU = (long long)BROWS * UDIM;
}

// ------------------------------ PTX helpers --------------------------------
__device__ __forceinline__ uint32_t smem_u32(const void* p) {
    uint32_t a;
    asm("{ .reg .u64 t; cvta.to.shared.u64 t, %1; cvt.u32.u64 %0, t; }" : "=r"(a) : "l"(p));
    return a;
}
__device__ __forceinline__ void cp16(uint32_t s, const void* g) {
    asm volatile("cp.async.cg.shared.global [%0], [%1], 16;" :: "r"(s), "l"(g));
}
#define CP_COMMIT() asm volatile("cp.async.commit_group;" ::: "memory")
#define CP_WAIT0()  asm volatile("cp.async.wait_group 0;" ::: "memory")
#define LDSM4(r0,r1,r2,r3,a) \
    asm volatile("ldmatrix.sync.aligned.m8n8.x4.shared.b16 {%0,%1,%2,%3}, [%4];" \
        : "=r"(r0),"=r"(r1),"=r"(r2),"=r"(r3) : "r"(a))
#define MMA(d,a,b) \
    asm volatile("mma.sync.aligned.m16n8k16.row.col.f32.bf16.bf16.f32 " \
        "{%0,%1,%2,%3},{%4,%5,%6,%7},{%8,%9},{%0,%1,%2,%3};" \
        : "+f"((d)[0]),"+f"((d)[1]),"+f"((d)[2]),"+f"((d)[3]) \
        : "r"((a)[0]),"r"((a)[1]),"r"((a)[2]),"r"((a)[3]),"r"((b)[0]),"r"((b)[1]))

__device__ __forceinline__ uint32_t packhl(float a, float b, bool lo) {
    if (lo) {
        a -= __bfloat162float(__float2bfloat16(a));
        b -= __bfloat162float(__float2bfloat16(b));
    }
    __nv_bfloat162 h2 = __float22bfloat162_rn(make_float2(a, b));
    return *(uint32_t*)&h2;
}

// ------------------------------ scratch ------------------------------------
__device__ __nv_bfloat16 g_inh[2LL*4096*2048], g_inl[2LL*4096*2048];   // split inputs
__device__ __nv_bfloat16 g_cth[4096*512],      g_ctl[4096*512];        // split crohis_tm
__device__ __nv_bfloat16 g_BWh[2*256*2048], g_BWl[2*256*2048];
__device__ __nv_bfloat16 g_BPh[2*256*512],  g_BPl[2*256*512];
__device__ __nv_bfloat16 g_BVh[2*256*256],  g_BVl[2*256*256];
__device__ __nv_bfloat16 g_BDh[512*512],    g_BDl[512*512];
__device__ __nv_bfloat16 g_BCh[512*512],    g_BCl[512*512];
__device__ __nv_bfloat16 g_BKh[2*1536*512], g_BKl[2*1536*512];
__device__ __nv_bfloat16 g_BRh[512*512],    g_BRl[512*512];
__device__ float         g_embf[4096*512];
__device__ __nv_bfloat16 g_embh[4096*512],  g_embl[4096*512];
__device__ float         g_Sf[2*4096*256],  g_Vf[2*4096*256];
__device__ __nv_bfloat16 g_xhh[2*4096*512], g_xhl[2*4096*512];         // [x ; h_prev]
__device__ float         g_hprev[4096*512];
__device__ __nv_bfloat16 g_croh[4096*512],  g_crol[4096*512];
__device__ float         g_mxi[2LL*4096*1536];
__device__ __nv_bfloat16 g_rhh[4096*512],   g_rhl[4096*512];
__device__ float         g_mh[4096*512];
__device__ float         g_zbias[1536];                                // stays zero

// ------------------- transpose + bf16 hi/lo split (weights) ----------------
__global__ void tsplit(const float* __restrict__ src, int srcld, int Krows, int N,
                       __nv_bfloat16* __restrict__ dh, __nv_bfloat16* __restrict__ dl,
                       int dstld, int koff, int Kwrite)
{
    __shared__ float t[32][33];
    int kt = blockIdx.y * 32, nt = blockIdx.x * 32;
    int tx = threadIdx.x, ty = threadIdx.y;   // (32,8)
    #pragma unroll
    for (int i = 0; i < 32; i += 8) {
        int k = kt + ty + i, n = nt + tx;
        t[ty + i][tx] = (k < Krows && n < N) ? src[(size_t)k * srcld + n] : 0.f;
    }
    __syncthreads();
    #pragma unroll
    for (int i = 0; i < 32; i += 8) {
        int n = nt + ty + i, k = kt + tx;
        if (n < N && k < Kwrite) {
            float f = t[tx][ty + i];
            __nv_bfloat16 h = __float2bfloat16(f);
            dh[(size_t)n * dstld + koff + k] = h;
            dl[(size_t)n * dstld + koff + k] = __float2bfloat16(f - __bfloat162float(h));
        }
    }
}

// ------------------- activation splits (no transpose) -----------------------
__global__ void split_inputs(const float* __restrict__ in)
{
    long long i = (long long)blockIdx.x * blockDim.x + threadIdx.x;  // 2*4096*256
    if (i >= 2LL * 4096 * 256) return;
    int c8 = (int)(i & 255);
    long long zr = i >> 8;               // z*4096 + row
    int row = (int)(zr & 4095);
    int z   = (int)(zr >> 12);
    const float* src = in + (size_t)row * 4000 + z * 2000 + c8 * 8;
    long long o = zr * 2048 + c8 * 8;
    #pragma unroll
    for (int e = 0; e < 8; ++e) {
        int c = c8 * 8 + e;
        float f = (c < 2000) ? src[e] : 0.f;
        __nv_bfloat16 h = __float2bfloat16(f);
        g_inh[o + e] = h;
        g_inl[o + e] = __float2bfloat16(f - __bfloat162float(h));
    }
}
__global__ void fsplit(const float* __restrict__ src,
                       __nv_bfloat16* __restrict__ dh, __nv_bfloat16* __restrict__ dl,
                       long long n)
{
    long long i = (long long)blockIdx.x * blockDim.x + threadIdx.x;
    if (i >= n) return;
    float f = src[i];
    __nv_bfloat16 h = __float2bfloat16(f);
    dh[i] = h;
    dl[i] = __float2bfloat16(f - __bfloat162float(h));
}

// ------------------------------ mma.sync GEMM -------------------------------
// C[M,N] = (Ah+Al)@(Bh+Bl)^T, 3 passes (hh, lh, hl) into fp32 accumulators.
// A: [M][lda] bf16 hi/lo.  B: [N][K] bf16 hi/lo.  Tile 128x128, k-chunk 32.
// EPI: 0 store, 1 +bias, 2 tanh(+bias), 3 add+tanh(+bias)
template <int EPI>
__global__ void __launch_bounds__(256)
mma_gemm(const __nv_bfloat16* Ahi_, const __nv_bfloat16* Alo_, long long lda, long long aZ,
         const __nv_bfloat16* Bhi_, const __nv_bfloat16* Blo_, long long bZ,
         float* C, long long ldc, long long cZ, __nv_bfloat16* Chi, __nv_bfloat16* Clo,
         int K, const float* bias0, const float* bias1,
         const float* add, long long ldadd, int skipZ, int skipXfrom)
{
    const int z = blockIdx.z, tn = blockIdx.x, tm = blockIdx.y;
    if (z == skipZ && tn >= skipXfrom) return;

    __shared__ __align__(16) uint8_t smA[2][128 * 80];
    __shared__ __align__(16) uint8_t smB[2][128 * 80];

    const int tid = threadIdx.x, wid = tid >> 5, lane = tid & 31;
    const int m0 = tm * 128, n0 = tn * 128;
    const int wm = wid & 3, wn = wid >> 2;

    const __nv_bfloat16* Ahi = Ahi_ + z * aZ;
    const __nv_bfloat16* Alo = Alo_ + z * aZ;
    const __nv_bfloat16* Bhi = Bhi_ + z * bZ;
    const __nv_bfloat16* Blo = Blo_ + z * bZ;
    if (C)   C   += z * cZ;
    if (Chi) { Chi += z * cZ; Clo += z * cZ; }
    const float* biasp = (z == 0) ? bias0 : bias1;

    uint32_t sA[2] = {smem_u32(smA[0]), smem_u32(smA[1])};
    uint32_t sB[2] = {smem_u32(smB[0]), smem_u32(smB[1])};
    // ldmatrix base addresses (per buffer)
    uint32_t aB_[2], bB_[2];
    #pragma unroll
    for (int b = 0; b < 2; ++b) {
        aB_[b] = sA[b] + (wm * 32 + (lane & 15)) * 80 + (lane >> 4) * 16;
        bB_[b] = sB[b] + (wn * 64 + (lane & 7) + ((lane >> 4) & 1) * 8) * 80
                       + ((lane >> 3) & 1) * 16;
    }
    const int ldr = tid >> 2, ldseg = tid & 3;   // 64 rows per 256 threads

    float acc[2][8][4];
    #pragma unroll
    for (int a = 0; a < 2; ++a)
        #pragma unroll
        for (int b = 0; b < 8; ++b)
            #pragma unroll
            for (int c = 0; c < 4; ++c) acc[a][b][c] = 0.f;

    const int nch = K / 32, total = 3 * nch;

    auto issue = [&](int cc, int buf) {
        const int p = cc / nch, ko = (cc % nch) * 32;
        const __nv_bfloat16* As = (p == 1) ? Alo : Ahi;
        const __nv_bfloat16* Bs = (p == 2) ? Blo : Bhi;
        #pragma unroll
        for (int it = 0; it < 2; ++it) {
            int r = ldr + it * 64;
            uint32_t so = r * 80 + ldseg * 16;
            cp16(sA[buf] + so, As + (size_t)(m0 + r) * lda + ko + ldseg * 8);
            cp16(sB[buf] + so, Bs + (size_t)(n0 + r) * K   + ko + ldseg * 8);
        }
        CP_COMMIT();
    };

    issue(0, 0);
    for (int cc = 0; cc < total; ++cc) {
        const int buf = cc & 1;
        CP_WAIT0();
        __syncthreads();
        if (cc + 1 < total) issue(cc + 1, buf ^ 1);
        // compute chunk cc from buf
        const uint32_t aB = aB_[buf], bB = bB_[buf];
        #pragma unroll
        for (int s = 0; s < 2; ++s) {
            uint32_t a0[4], a1[4], b[8][2];
            LDSM4(a0[0], a0[1], a0[2], a0[3], aB + s * 32);
            LDSM4(a1[0], a1[1], a1[2], a1[3], aB + 16 * 80 + s * 32);
            #pragma unroll
            for (int np = 0; np < 4; ++np)
                LDSM4(b[2*np][0], b[2*np][1], b[2*np+1][0], b[2*np+1][1],
                      bB + np * 16 * 80 + s * 32);
            #pragma unroll
            for (int nt = 0; nt < 8; ++nt) {
                MMA(acc[0][nt], a0, b[nt]);
                MMA(acc[1][nt], a1, b[nt]);
            }
        }
        __syncthreads();
    }

    // ------------------------------ epilogue --------------------------------
    const int tig = lane & 3, gid = lane >> 2;
    #pragma unroll
    for (int mt = 0; mt < 2; ++mt) {
        #pragma unroll
        for (int half = 0; half < 2; ++half) {
            const int row = m0 + wm * 32 + mt * 16 + gid + half * 8;
            #pragma unroll
            for (int nt = 0; nt < 8; ++nt) {
                const int col = n0 + wn * 64 + nt * 8 + 2 * tig;
                float x0 = acc[mt][nt][half * 2 + 0];
                float x1 = acc[mt][nt][half * 2 + 1];
                if (EPI == 1)      { x0 += biasp[col]; x1 += biasp[col + 1]; }
                else if (EPI == 2) { x0 = tanhf(x0 + biasp[col]); x1 = tanhf(x1 + biasp[col + 1]); }
                else if (EPI == 3) {
                    x0 = add[(size_t)row * ldadd + col]     + tanhf(x0 + biasp[col]);
                    x1 = add[(size_t)row * ldadd + col + 1] + tanhf(x1 + biasp[col + 1]);
                }
                if (C) *(float2*)(C + (size_t)row * ldc + col) = make_float2(x0, x1);
                if (Chi) {
                    *(uint32_t*)(Chi + (size_t)row * ldc + col) = packhl(x0, x1, false);
                    *(uint32_t*)(Clo + (size_t)row * ldc + col) = packhl(x0, x1, true);
                }
            }
        }
    }
}

// ------------------------------ attention + crohis_new ----------------------
__global__ void __launch_bounds__(256)
attn_kernel(const float* __restrict__ crohis_tm, float* __restrict__ out_crohis)
{
    __shared__ float red[256];
    const int row = blockIdx.x, c = threadIdx.x;
    const float* emb = g_embf + (long long)row * 512;
    #pragma unroll
    for (int side = 0; side < 2; side++) {
        const float* S = g_Sf + (long long)side * (BROWS*256) + (long long)row * 256;
        const float* V = g_Vf + (long long)side * (BROWS*256) + (long long)row * 256;
        float l = tanhf(S[c]) * V[c];
        red[c] = l; __syncthreads();
        #pragma unroll
        for (int s = 128; s > 0; s >>= 1) { if (c < s) red[c] = fmaxf(red[c], red[c+s]); __syncthreads(); }
        float m = red[0]; __syncthreads();
        float e = __expf(l - m);
        red[c] = e; __syncthreads();
        #pragma unroll
        for (int s = 128; s > 0; s >>= 1) { if (c < s) red[c] += red[c+s]; __syncthreads(); }
        float ssum = red[0]; __syncthreads();
        int col = side * 256 + c;
        float xv = emb[col] * (e / ssum);
        long long gi = (long long)row * 512 + col;
        __nv_bfloat16 h = __float2bfloat16(xv);
        g_xhh[gi] = h;
        g_xhl[gi] = __float2bfloat16(xv - __bfloat162float(h));
        out_crohis[gi] = 0.5f * crohis_tm[gi] + 0.5f * xv;
    }
}

__global__ void rgate_kernel()
{
    int idx = blockIdx.x * blockDim.x + threadIdx.x;
    if (idx >= BROWS * UDIM) return;
    int row = idx >> 9, col = idx & 511;
    const float* mx = g_mxi + (long long)row * THREEU;
    const float* mi = g_mxi + (long long)BROWS * THREEU + (long long)row * THREEU;
    float r = 1.0f / (1.0f + __expf(-(mx[col + 512] + mi[col + 512])));
    float rh = r * g_hprev[idx];
    __nv_bfloat16 h = __float2bfloat16(rh);
    g_rhh[idx] = h;
    g_rhl[idx] = __float2bfloat16(rh - __bfloat162float(h));
}

__global__ void gru_kernel(float* __restrict__ h_out)
{
    int idx = blockIdx.x * blockDim.x + threadIdx.x;
    if (idx >= BROWS * UDIM) return;
    int row = idx >> 9, col = idx & 511;
    const float* mx = g_mxi + (long long)row * THREEU;
    const float* mi = g_mxi + (long long)BROWS * THREEU + (long long)row * THREEU;
    float z  = 1.0f / (1.0f + __expf(-(mx[col] + mi[col])));
    float hp = g_hprev[idx];
    float hh = tanhf(mx[col + 1024] + g_mh[idx]);
    h_out[idx] = z * hp + (1.0f - z) * hh;
}

// ------------------------------ launch --------------------------------------
extern "C" void kernel_launch(void* const* d_in, const int* in_sizes, int n_in,
                              void* d_out, int out_size)
{
    const float* inputs    = (const float*)d_in[0];
    const float* h_tm1     = (const float*)d_in[1];
    const float* crohis_tm = (const float*)d_in[2];
    const float* W1   = (const float*)d_in[3];
    const float* W2   = (const float*)d_in[4];
    const float* w12  = (const float*)d_in[5];
    const float* u12  = (const float*)d_in[6];
    const float* v12  = (const float*)d_in[7];
    const float* w21  = (const float*)d_in[8];
    const float* u21  = (const float*)d_in[9];
    const float* v21  = (const float*)d_in[10];
    const float* croW = (const float*)d_in[11];
    const float* croB = (const float*)d_in[12];
    const float* decompW = (const float*)d_in[13];
    const float* decompB = (const float*)d_in[14];
    const float* kern  = (const float*)d_in[15];
    const float* rkern = (const float*)d_in[16];
    const float* bias  = (const float*)d_in[17];
    float* out = (float*)d_out;

    __nv_bfloat16 *pINh,*pINl,*pCTh,*pCTl,*pBWh,*pBWl,*pBPh,*pBPl,*pBVh,*pBVl,
                  *pBDh,*pBDl,*pBCh,*pBCl,*pBKh,*pBKl,*pBRh,*pBRl,
                  *pEh,*pEl,*pXHh,*pXHl,*pCRh,*pCRl,*pRHh,*pRHl;
    float *pEf,*pSf,*pVf,*pHP,*pMXI,*pMH,*pZB;
    cudaGetSymbolAddress((void**)&pINh,g_inh); cudaGetSymbolAddress((void**)&pINl,g_inl);
    cudaGetSymbolAddress((void**)&pCTh,g_cth); cudaGetSymbolAddress((void**)&pCTl,g_ctl);
    cudaGetSymbolAddress((void**)&pBWh,g_BWh); cudaGetSymbolAddress((void**)&pBWl,g_BWl);
    cudaGetSymbolAddress((void**)&pBPh,g_BPh); cudaGetSymbolAddress((void**)&pBPl,g_BPl);
    cudaGetSymbolAddress((void**)&pBVh,g_BVh); cudaGetSymbolAddress((void**)&pBVl,g_BVl);
    cudaGetSymbolAddress((void**)&pBDh,g_BDh); cudaGetSymbolAddress((void**)&pBDl,g_BDl);
    cudaGetSymbolAddress((void**)&pBCh,g_BCh); cudaGetSymbolAddress((void**)&pBCl,g_BCl);
    cudaGetSymbolAddress((void**)&pBKh,g_BKh); cudaGetSymbolAddress((void**)&pBKl,g_BKl);
    cudaGetSymbolAddress((void**)&pBRh,g_BRh); cudaGetSymbolAddress((void**)&pBRl,g_BRl);
    cudaGetSymbolAddress((void**)&pEf,g_embf);
    cudaGetSymbolAddress((void**)&pEh,g_embh); cudaGetSymbolAddress((void**)&pEl,g_embl);
    cudaGetSymbolAddress((void**)&pSf,g_Sf);   cudaGetSymbolAddress((void**)&pVf,g_Vf);
    cudaGetSymbolAddress((void**)&pXHh,g_xhh); cudaGetSymbolAddress((void**)&pXHl,g_xhl);
    cudaGetSymbolAddress((void**)&pHP,g_hprev);
    cudaGetSymbolAddress((void**)&pCRh,g_croh); cudaGetSymbolAddress((void**)&pCRl,g_crol);
    cudaGetSymbolAddress((void**)&pMXI,g_mxi);
    cudaGetSymbolAddress((void**)&pRHh,g_rhh); cudaGetSymbolAddress((void**)&pRHl,g_rhl);
    cudaGetSymbolAddress((void**)&pMH,g_mh);   cudaGetSymbolAddress((void**)&pZB,g_zbias);

    dim3 tb(32, 8);
    auto T = [&](const float* s, int sld, int Kr, int N,
                 __nv_bfloat16* dh, __nv_bfloat16* dl, int dld, int ko, int Kw) {
        tsplit<<<dim3((N+31)/32, (Kw+31)/32), tb>>>(s, sld, Kr, N, dh, dl, dld, ko, Kw);
    };
    // weights -> [N][K] bf16 hi/lo (zero-padded K where needed)
    T(W1, 256, 2000, 256, pBWh,            pBWl,            2048, 0, 2048);
    T(W2, 256, 2000, 256, pBWh+256*2048,   pBWl+256*2048,   2048, 0, 2048);
    T(w12, 256, 256, 256, pBPh,            pBPl,            512, 0,   256);
    T(u12, 256, 256, 256, pBPh,            pBPl,            512, 256, 256);
    T(u21, 256, 256, 256, pBPh+256*512,    pBPl+256*512,    512, 0,   256);
    T(w21, 256, 256, 256, pBPh+256*512,    pBPl+256*512,    512, 256, 256);
    T(v12, 256, 256, 256, pBVh,            pBVl,            256, 0,   256);
    T(v21, 256, 256, 256, pBVh+256*256,    pBVl+256*256,    256, 0,   256);
    T(decompW, 512, 512, 512, pBDh, pBDl, 512, 0, 512);
    T(croW,    512, 512, 512, pBCh, pBCl, 512, 0, 512);
    T(kern,  1536, 512, 1536, pBKh,          pBKl,          512, 0, 512);
    T(rkern, 1536, 512, 1536, pBKh+1536*512, pBKl+1536*512, 512, 0, 512);
    T(rkern+1024, 1536, 512, 512, pBRh, pBRl, 512, 0, 512);

    // activation splits
    split_inputs<<<(2*4096*256 + 255)/256, 256>>>(inputs);
    fsplit<<<(int)((BU + 255)/256), 256>>>(crohis_tm, pCTh, pCTl, BU);

    // emb = inputs @ W  (z-batched, K padded to 2048)
    mma_gemm<0><<<dim3(2,32,2), 256>>>(
        pINh, pINl, 2048, 4096LL*2048, pBWh, pBWl, (long long)256*2048,
        pEf, 512, 256, pEh, pEl, 2048, nullptr, nullptr, nullptr, 0, -1, 0);
    // S = emb @ [w;u]   (K=512)
    mma_gemm<0><<<dim3(2,32,2), 256>>>(
        pEh, pEl, 512, 0, pBPh, pBPl, (long long)256*512,
        pSf, 256, (long long)BROWS*256, nullptr, nullptr, 512,
        nullptr, nullptr, nullptr, 0, -1, 0);
    // V12 = emb2 @ v12, V21 = emb1 @ v21  (K=256; aZ=-256 selects emb half)
    mma_gemm<0><<<dim3(2,32,2), 256>>>(
        pEh+256, pEl+256, 512, -256, pBVh, pBVl, (long long)256*256,
        pVf, 256, (long long)BROWS*256, nullptr, nullptr, 256,
        nullptr, nullptr, nullptr, 0, -1, 0);
    // attention + crohis_new (second half of d_out)
    attn_kernel<<<BROWS, 256>>>(crohis_tm, out + BU);
    // cro = tanh(crohis_tm @ decompW + decompB)  -> bf16 hi/lo
    mma_gemm<2><<<dim3(4,32,1), 256>>>(
        pCTh, pCTl, 512, 0, pBDh, pBDl, 0,
        nullptr, 512, 0, pCRh, pCRl, 512, decompB, decompB, nullptr, 0, -1, 0);
    // h_prev = h_tm1 + tanh(cro @ croW + croB)  -> fp32 + hi/lo (xh 2nd half)
    mma_gemm<3><<<dim3(4,32,1), 256>>>(
        pCRh, pCRl, 512, 0, pBCh, pBCl, 0,
        pHP, 512, 0, pXHh + BU, pXHl + BU, 512, croB, croB, h_tm1, 512, -1, 0);
    // mx = x @ kernel + bias ; mi(first 1024 cols) = h_prev @ rkern
    mma_gemm<1><<<dim3(12,32,2), 256>>>(
        pXHh, pXHl, 512, BU, pBKh, pBKl, (long long)1536*512,
        pMXI, 1536, (long long)BROWS*1536, nullptr, nullptr, 512,
        bias, pZB, nullptr, 0, 1, 8);
    // r gate, rh = r*h_prev (hi/lo)
    rgate_kernel<<<(BROWS*UDIM + 255)/256, 256>>>();
    // mh = rh @ rkern[:, 2U:]
    mma_gemm<0><<<dim3(4,32,1), 256>>>(
        pRHh, pRHl, 512, 0, pBRh, pBRl, 0,
        pMH, 512, 0, nullptr, nullptr, 512, nullptr, nullptr, nullptr, 0, -1, 0);
    // GRU combine -> h (first half of d_out)
    gru_kernel<<<(BROWS*UDIM + 255)/256, 256>>>(out);
}